// round 2
// baseline (speedup 1.0000x reference)
#include <cuda_runtime.h>
#include <cuda_fp16.h>
#include <cstdint>

#define M_DIM 4096
#define N_DIM 8192
#define K_DIM 2048

#define BM 128
#define BN 128
#define BK 32
#define LDS 40                    // smem row stride in halves (80B, 16B-aligned, conflict-free ldmatrix)
#define A_HALVES (BM * LDS)       // 5120
#define STAGE_HALVES (2 * A_HALVES) // A + B per stage = 10240 halves = 20480 B
#define NIT (K_DIM / BK)          // 64

// Static device scratch (allocation-free rule): fp16 weights + fp16 activations
__device__ __align__(16) __half g_w[(size_t)N_DIM * K_DIM];  // 32 MB
__device__ __align__(16) __half g_x[(size_t)M_DIM * K_DIM];  // 16 MB

__constant__ float c_lut[16] = {
    -1.0f, -0.5f, -0.333333f, -0.2f, -0.142857f, -0.090909f, -0.076923f,
    0.0f, 0.076923f, 0.090909f, 0.142857f, 0.2f, 0.333333f, 0.5f, 1.0f, 0.0f};

// ---------------------------------------------------------------------------
// Dequant: int32 LUT indices -> fp16 weights (4 per thread)
// ---------------------------------------------------------------------------
__global__ __launch_bounds__(256) void dequant_kernel(const int* __restrict__ gi,
                                                      const float* __restrict__ scale_p) {
    float s = *scale_p;
    size_t i = ((size_t)blockIdx.x * blockDim.x + threadIdx.x) * 4;
    int4 v = *reinterpret_cast<const int4*>(gi + i);
    __half2 h0 = __floats2half2_rn(c_lut[v.x] * s, c_lut[v.y] * s);
    __half2 h1 = __floats2half2_rn(c_lut[v.z] * s, c_lut[v.w] * s);
    uint2 o;
    o.x = *reinterpret_cast<uint32_t*>(&h0);
    o.y = *reinterpret_cast<uint32_t*>(&h1);
    *reinterpret_cast<uint2*>(g_w + i) = o;
}

// ---------------------------------------------------------------------------
// Convert activations fp32 -> fp16 (4 per thread)
// ---------------------------------------------------------------------------
__global__ __launch_bounds__(256) void xconv_kernel(const float* __restrict__ x) {
    size_t i = ((size_t)blockIdx.x * blockDim.x + threadIdx.x) * 4;
    float4 v = *reinterpret_cast<const float4*>(x + i);
    __half2 h0 = __floats2half2_rn(v.x, v.y);
    __half2 h1 = __floats2half2_rn(v.z, v.w);
    uint2 o;
    o.x = *reinterpret_cast<uint32_t*>(&h0);
    o.y = *reinterpret_cast<uint32_t*>(&h1);
    *reinterpret_cast<uint2*>(g_x + i) = o;
}

// ---------------------------------------------------------------------------
// GEMM helpers
// ---------------------------------------------------------------------------
__device__ __forceinline__ void cp16(__half* dst, const __half* src) {
    uint32_t d = (uint32_t)__cvta_generic_to_shared(dst);
    asm volatile("cp.async.cg.shared.global [%0], [%1], 16;\n" :: "r"(d), "l"(src));
}

__device__ __forceinline__ void ldsm4(uint32_t* r, const __half* p) {
    uint32_t a = (uint32_t)__cvta_generic_to_shared(p);
    asm volatile("ldmatrix.sync.aligned.m8n8.x4.shared.b16 {%0,%1,%2,%3}, [%4];\n"
                 : "=r"(r[0]), "=r"(r[1]), "=r"(r[2]), "=r"(r[3]) : "r"(a));
}

__device__ __forceinline__ void mma16816(float* c, const uint32_t* a, const uint32_t* b) {
    asm volatile(
        "mma.sync.aligned.m16n8k16.row.col.f32.f16.f16.f32 "
        "{%0,%1,%2,%3}, {%4,%5,%6,%7}, {%8,%9}, {%0,%1,%2,%3};\n"
        : "+f"(c[0]), "+f"(c[1]), "+f"(c[2]), "+f"(c[3])
        : "r"(a[0]), "r"(a[1]), "r"(a[2]), "r"(a[3]), "r"(b[0]), "r"(b[1]));
}

// ---------------------------------------------------------------------------
// GEMM: C[M,N] = g_x[M,K] * g_w[N,K]^T, fp16 in / fp32 accum / fp32 out
// 128x128x32 block tile, 8 warps (4 M-slices x 2 N-slices, each 32x64)
// ---------------------------------------------------------------------------
__global__ __launch_bounds__(256, 2) void gemm_kernel(float* __restrict__ out) {
    extern __shared__ __half sm[];

    const int tid = threadIdx.x;
    const int warp = tid >> 5;
    const int lane = tid & 31;
    const int wm = warp & 3;   // M slice (32 rows)
    const int wn = warp >> 2;  // N slice (64 cols)
    const int m0 = blockIdx.y * BM;
    const int n0 = blockIdx.x * BN;

    // global load coordinates: each thread copies 2 chunks of 16B per tile (A and B)
    const int lr = tid >> 2;            // rows 0..63 (second chunk uses +64)
    const int lc = (tid & 3) * 8;       // half offset in row

    float acc[2][8][4];
#pragma unroll
    for (int i = 0; i < 2; i++)
#pragma unroll
        for (int j = 0; j < 8; j++)
#pragma unroll
            for (int k = 0; k < 4; k++) acc[i][j][k] = 0.0f;

    // stage load
    auto load_stage = [&](int s, int k0) {
        __half* a = sm + s * STAGE_HALVES;
        __half* b = a + A_HALVES;
        cp16(a + lr * LDS + lc,        g_x + (size_t)(m0 + lr) * K_DIM + k0 + lc);
        cp16(a + (lr + 64) * LDS + lc, g_x + (size_t)(m0 + lr + 64) * K_DIM + k0 + lc);
        cp16(b + lr * LDS + lc,        g_w + (size_t)(n0 + lr) * K_DIM + k0 + lc);
        cp16(b + (lr + 64) * LDS + lc, g_w + (size_t)(n0 + lr + 64) * K_DIM + k0 + lc);
        asm volatile("cp.async.commit_group;\n");
    };

    load_stage(0, 0);

    for (int it = 0; it < NIT; ++it) {
        if (it + 1 < NIT) {
            load_stage((it + 1) & 1, (it + 1) * BK);
            asm volatile("cp.async.wait_group 1;\n");
        } else {
            asm volatile("cp.async.wait_group 0;\n");
        }
        __syncthreads();

        const __half* a_s = sm + (it & 1) * STAGE_HALVES;
        const __half* b_s = a_s + A_HALVES;

#pragma unroll
        for (int kk = 0; kk < BK; kk += 16) {
            uint32_t af[2][4];
#pragma unroll
            for (int mt = 0; mt < 2; mt++) {
                const __half* p = a_s + (wm * 32 + mt * 16 + (lane & 15)) * LDS
                                      + kk + (lane >> 4) * 8;
                ldsm4(af[mt], p);
            }
            uint32_t bf[8][2];
#pragma unroll
            for (int np = 0; np < 4; np++) {
                const __half* p = b_s + (wn * 64 + np * 16 + (lane & 7) + ((lane >> 4) & 1) * 8) * LDS
                                      + kk + ((lane >> 3) & 1) * 8;
                uint32_t r[4];
                ldsm4(r, p);
                bf[np * 2][0] = r[0]; bf[np * 2][1] = r[1];
                bf[np * 2 + 1][0] = r[2]; bf[np * 2 + 1][1] = r[3];
            }
#pragma unroll
            for (int mt = 0; mt < 2; mt++)
#pragma unroll
                for (int nt = 0; nt < 8; nt++)
                    mma16816(acc[mt][nt], af[mt], bf[nt]);
        }
        __syncthreads();
    }

    // epilogue: direct fp32 stores (float2 per fragment half)
#pragma unroll
    for (int mt = 0; mt < 2; mt++) {
#pragma unroll
        for (int nt = 0; nt < 8; nt++) {
            int row = m0 + wm * 32 + mt * 16 + (lane >> 2);
            int col = n0 + wn * 64 + nt * 8 + (lane & 3) * 2;
            float2 v0 = make_float2(acc[mt][nt][0], acc[mt][nt][1]);
            float2 v1 = make_float2(acc[mt][nt][2], acc[mt][nt][3]);
            *reinterpret_cast<float2*>(out + (size_t)row * N_DIM + col) = v0;
            *reinterpret_cast<float2*>(out + (size_t)(row + 8) * N_DIM + col) = v1;
        }
    }
}

// ---------------------------------------------------------------------------
// kernel_launch
// ---------------------------------------------------------------------------
extern "C" void kernel_launch(void* const* d_in, const int* in_sizes, int n_in,
                              void* d_out, int out_size) {
    const float* x = (const float*)d_in[0];
    const int* gi = (const int*)d_in[1];
    const float* scale = (const float*)d_in[2];
    float* out = (float*)d_out;

    dequant_kernel<<<(N_DIM * K_DIM / 4) / 256, 256>>>(gi, scale);
    xconv_kernel<<<(M_DIM * K_DIM / 4) / 256, 256>>>(x);

    dim3 grid(N_DIM / BN, M_DIM / BM);  // (64, 32)
    size_t smem = 2 * STAGE_HALVES * sizeof(__half);  // 40960 B
    gemm_kernel<<<grid, 256, smem>>>(out);
}